// round 14
// baseline (speedup 1.0000x reference)
#include <cuda_runtime.h>
#include <cuda_fp16.h>
#include <cstdint>

#define BB 8
#define SS 2048
#define DD 1024
#define HH 64
#define MM (BB*SS)
#define GRID 512

// Scratch (fp16): Q pre-scaled by log2e/32; K,V hi-only
__device__ __align__(16) __half g_Qh[MM*HH];
__device__ __align__(16) __half g_Kh[MM*HH];
__device__ __align__(16) __half g_Vh[MM*HH];
// W hi (fp16 rn): [3][64][1024], mat order {Q,K,V}
__device__ __align__(16) __half g_Wh[3*HH*DD];
// grid barrier ticket counter (monotonic across launches; tickets stay
// GRID-aligned because every launch completes all its barriers)
__device__ unsigned g_bar;

// ---------------------------------------------------------------------------
// helpers
// ---------------------------------------------------------------------------
__device__ __forceinline__ uint32_t pack2h(float lo, float hi) {
    uint32_t r;
    asm("cvt.rn.f16x2.f32 %0, %1, %2;" : "=r"(r) : "f"(hi), "f"(lo));
    return r;
}

__device__ __forceinline__ void ldm_x4(uint32_t* r, uint32_t addr) {
    asm volatile("ldmatrix.sync.aligned.m8n8.x4.shared.b16 {%0,%1,%2,%3}, [%4];"
                 : "=r"(r[0]), "=r"(r[1]), "=r"(r[2]), "=r"(r[3]) : "r"(addr));
}
__device__ __forceinline__ void ldm_x4_t(uint32_t* r, uint32_t addr) {
    asm volatile("ldmatrix.sync.aligned.m8n8.x4.trans.shared.b16 {%0,%1,%2,%3}, [%4];"
                 : "=r"(r[0]), "=r"(r[1]), "=r"(r[2]), "=r"(r[3]) : "r"(addr));
}

__device__ __forceinline__ void cp16(uint32_t dst, const void* src) {
    asm volatile("cp.async.cg.shared.global [%0], [%1], 16;"
                 :: "r"(dst), "l"(src) : "memory");
}
#define CP_COMMIT() asm volatile("cp.async.commit_group;" ::: "memory")
#define CP_WAIT0()  asm volatile("cp.async.wait_group 0;" ::: "memory")

// smem fp16 tiles: row stride 144 bytes (72 halves) -> ldmatrix conflict-free
#define LDB 144

__device__ __forceinline__ uint32_t ldm_addr(uint32_t base, int row0, int col0) {
    int l = threadIdx.x & 31;
    int r = row0 + (l & 7) + ((l >> 3) & 1) * 8;
    int c = col0 + (l >> 4) * 8;
    return base + r * LDB + c * 2;
}
__device__ __forceinline__ uint32_t ldm_addr_b(uint32_t base, int row0, int col0) {
    int l = threadIdx.x & 31;
    int r = row0 + (l & 7) + (l >> 4) * 8;
    int c = col0 + ((l >> 3) & 1) * 8;
    return base + r * LDB + c * 2;
}

__device__ __forceinline__ void mma_f16(float* d, const uint32_t* a, const uint32_t* b) {
    asm volatile(
        "mma.sync.aligned.m16n8k16.row.col.f32.f16.f16.f32 "
        "{%0,%1,%2,%3}, {%4,%5,%6,%7}, {%8,%9}, {%0,%1,%2,%3};"
        : "+f"(d[0]), "+f"(d[1]), "+f"(d[2]), "+f"(d[3])
        : "r"(a[0]), "r"(a[1]), "r"(a[2]), "r"(a[3]), "r"(b[0]), "r"(b[1]));
}

// 2^x via magic-round + deg-4 Taylor. No clamp: inputs bounded (masked = -126).
__device__ __forceinline__ float fast_exp2(float x) {
    float r = x + 12582912.0f;
    int ik = __float_as_int(r) - 0x4B400000;
    float f = x - (r - 12582912.0f);
    float p = fmaf(0.0096180f, f, 0.0555041f);
    p = fmaf(p, f, 0.2402265f);
    p = fmaf(p, f, 0.6931472f);
    p = fmaf(p, f, 1.0f);
    return __int_as_float(__float_as_int(p) + (ik << 23));
}

// Grid-wide barrier: ticket counter, all CTAs resident (single wave) so
// spinning is deadlock-free. Monotonic counter; release at next multiple
// of GRID above own ticket.
__device__ __forceinline__ void grid_barrier() {
    __syncthreads();
    __threadfence();
    if (threadIdx.x == 0) {
        unsigned tck = atomicAdd(&g_bar, 1u);
        unsigned rel = (tck / GRID + 1u) * GRID;
        unsigned v;
        do {
            asm volatile("ld.volatile.global.u32 %0, [%1];"
                         : "=r"(v) : "l"(&g_bar) : "memory");
        } while (v < rel);
        __threadfence();
    }
    __syncthreads();
}

// ---------------------------------------------------------------------------
// smem layout (shared across phases)
// proj phase: X at 0 (32*144=4608), W at 4608 (+192*144=27648) -> 32256
// attn phase: Q at 0 (4608), K/V double-buffer at 4608, lred at 41472
// ---------------------------------------------------------------------------
#define PBX   0
#define PBW   4608
#define AQ    0
#define ABUF  4608
#define PLANE 9216
#define STG   (2 * PLANE)
#define ALR   (ABUF + 2 * STG)   // 41472
#define ATOT  (ALR + 256)        // 41728

__global__ __launch_bounds__(128, 4) void fused_head(
    const float* __restrict__ X,
    const float* __restrict__ Wq,
    const float* __restrict__ Wk,
    const float* __restrict__ Wv,
    float* __restrict__ Outp)
{
    extern __shared__ char sm[];
    const uint32_t sb = (uint32_t)__cvta_generic_to_shared(sm);
    const int tid = threadIdx.x, wid = tid >> 5, lane = tid & 31;
    const int g = lane >> 2, t = lane & 3;
    const int bid = blockIdx.x;

    // ======================= Phase A: W f32 -> f16 =========================
    {
        int gid = bid * 128 + tid;          // 65536 threads, 49152 float4 jobs
        if (gid < 3 * 16384) {
            int mat = gid >> 14;            // 16384 float4 per matrix
            int idx4 = gid & 16383;
            const float* W = (mat == 0) ? Wq : ((mat == 1) ? Wk : Wv);
            float4 v = reinterpret_cast<const float4*>(W)[idx4];
            uint32_t* ph = reinterpret_cast<uint32_t*>(g_Wh);
            ph[mat * 32768 + idx4 * 2]     = pack2h(v.x, v.y);
            ph[mat * 32768 + idx4 * 2 + 1] = pack2h(v.z, v.w);
        }
    }
    grid_barrier();

    // ======================= Phase B: projection ===========================
    // CTA = 32 rows of X; warps 2m x 2n; warp tile 16 rows x 96 cols.
    {
        const int wm = wid >> 1, wn = wid & 1;
        const int m0 = bid * 32;

        float acc[6][2][4];
        #pragma unroll
        for (int a = 0; a < 6; a++)
            #pragma unroll
            for (int b = 0; b < 2; b++)
                #pragma unroll
                for (int d = 0; d < 4; d++) acc[a][b][d] = 0.f;

        for (int kc = 0; kc < 16; kc++) {
            const int kbase = kc * 64;
            // X chunk: 32 rows x 64 f32 -> rn f16 (512 float4, 4/thread)
            #pragma unroll
            for (int i = 0; i < 4; i++) {
                int id = tid + i * 128;
                int row = id >> 4, c4 = id & 15;
                float4 v = *reinterpret_cast<const float4*>(
                    X + (size_t)(m0 + row) * DD + kbase + c4 * 4);
                uint32_t off = row * LDB + c4 * 8;
                *reinterpret_cast<uint32_t*>(sm + PBX + off)     = pack2h(v.x, v.y);
                *reinterpret_cast<uint32_t*>(sm + PBX + off + 4) = pack2h(v.z, v.w);
            }
            // W chunk: 192 rows x 64 f16 (1536 uint4, 12/thread)
            #pragma unroll
            for (int i = 0; i < 12; i++) {
                int id = tid + i * 128;
                int row = id >> 3, c = id & 7;
                uint4 v = *reinterpret_cast<const uint4*>(
                    g_Wh + (size_t)row * DD + kbase + c * 8);
                *reinterpret_cast<uint4*>(sm + PBW + row * LDB + c * 16) = v;
            }
            __syncthreads();

            #pragma unroll
            for (int ks = 0; ks < 4; ks++) {
                uint32_t a[4];
                ldm_x4(a, ldm_addr(sb + PBX, wm * 16, ks * 16));
                #pragma unroll
                for (int bt = 0; bt < 6; bt++) {
                    uint32_t bh[4];
                    ldm_x4(bh, ldm_addr_b(sb + PBW, wn * 96 + bt * 16, ks * 16));
                    mma_f16(acc[bt][0], a, &bh[0]);
                    mma_f16(acc[bt][1], a, &bh[2]);
                }
            }
            __syncthreads();
        }

        // epilogue: fp16 hi-only; Q scaled by log2e/32
        #pragma unroll
        for (int bt = 0; bt < 6; bt++)
            #pragma unroll
            for (int fn = 0; fn < 2; fn++) {
                int gcol = wn * 96 + bt * 16 + fn * 8 + t * 2;
                int mat = gcol >> 6, col = gcol & 63;
                __half* gh = (mat == 0) ? g_Qh : ((mat == 1) ? g_Kh : g_Vh);
                const float scl = (mat == 0) ? (1.44269504f / 32.0f) : 1.0f;
                const float* c = acc[bt][fn];
                int r0 = m0 + wm * 16 + g;
                reinterpret_cast<uint32_t*>(gh)[((size_t)r0 * HH + col) >> 1] =
                    pack2h(c[0] * scl, c[1] * scl);
                reinterpret_cast<uint32_t*>(gh)[((size_t)(r0 + 8) * HH + col) >> 1] =
                    pack2h(c[2] * scl, c[3] * scl);
            }
    }
    grid_barrier();

    // ======================= Phase C: attention ============================
    {
        const int qw = wid >> 1, kw = wid & 1;

        // LPT snake schedule (same as round 13)
        int r = bid / 148, j = bid - r * 148;
        int i = (r < 3) ? (r * 148 + ((r & 1) ? (147 - j) : j)) : bid;
        const int qt = 31 - (i >> 4);
        const int sub = i & 15;
        const int b = sub >> 1, half = sub & 1;

        const int q0c = qt * 64 + half * 32;
        const size_t base = (size_t)b * SS;

        // prefetch K/V tile 0
        #pragma unroll
        for (int i2 = 0; i2 < 8; i2++) {
            int id = tid + i2 * 128;
            int plane = id >> 9, rem = id & 511;
            int row = rem >> 3, c = rem & 7;
            const __half* src = (plane == 0) ? g_Kh : g_Vh;
            cp16(sb + ABUF + plane * PLANE + row * LDB + c * 16,
                 src + (base + row) * HH + c * 8);
        }
        CP_COMMIT();

        // load Q tile (32 rows), hoist this warp's fragments
        #pragma unroll
        for (int i2 = 0; i2 < 2; i2++) {
            int id = tid + i2 * 128;
            int row = id >> 3, c = id & 7;
            *reinterpret_cast<uint4*>(sm + AQ + row * LDB + c * 16) =
                *reinterpret_cast<const uint4*>(g_Qh + (base + q0c + row) * HH + c * 8);
        }
        __syncthreads();
        uint32_t qa[4][4];
        #pragma unroll
        for (int hs = 0; hs < 4; hs++)
            ldm_x4(qa[hs], ldm_addr(sb + AQ, qw * 16, hs * 16));

        float o[8][4];
        #pragma unroll
        for (int i2 = 0; i2 < 8; i2++)
            #pragma unroll
            for (int j2 = 0; j2 < 4; j2++) o[i2][j2] = 0.f;
        float lsum0 = 0.f, lsum1 = 0.f;

        for (int kt = 0; kt <= qt; kt++) {
            const int k0 = kt * 64;
            CP_WAIT0();
            __syncthreads();

            if (kt < qt) {
                const int kn = k0 + 64;
                const uint32_t dstg = sb + ABUF + ((kt + 1) & 1) * STG;
                #pragma unroll
                for (int i2 = 0; i2 < 8; i2++) {
                    int id = tid + i2 * 128;
                    int plane = id >> 9, rem = id & 511;
                    int row = rem >> 3, c = rem & 7;
                    const __half* src = (plane == 0) ? g_Kh : g_Vh;
                    cp16(dstg + plane * PLANE + row * LDB + c * 16,
                         src + (base + kn + row) * HH + c * 8);
                }
            }
            CP_COMMIT();

            // lower half-tile diagonal: kw=1's cols fully masked -> skip
            if (kt == qt && half == 0 && kw == 1) continue;

            const uint32_t stg = sb + ABUF + (kt & 1) * STG;
            const uint32_t sKH = stg, sVH = stg + PLANE;

            float s[4][4];
            #pragma unroll
            for (int i2 = 0; i2 < 4; i2++)
                #pragma unroll
                for (int j2 = 0; j2 < 4; j2++) s[i2][j2] = 0.f;

            #pragma unroll
            for (int hs = 0; hs < 4; hs++) {
                uint32_t bh[4], bh2[4];
                ldm_x4(bh,  ldm_addr_b(sKH, kw * 32,      hs * 16));
                ldm_x4(bh2, ldm_addr_b(sKH, kw * 32 + 16, hs * 16));
                #pragma unroll
                for (int fn = 0; fn < 2; fn++) {
                    mma_f16(s[fn],     qa[hs], &bh[fn * 2]);
                    mma_f16(s[2 + fn], qa[hs], &bh2[fn * 2]);
                }
            }

            if (kt == qt) {
                #pragma unroll
                for (int f = 0; f < 4; f++) {
                    int kg = k0 + kw * 32 + f * 8 + t * 2;
                    int qg0 = q0c + qw * 16 + g, qg1 = qg0 + 8;
                    if (kg     > qg0) s[f][0] = -126.f;
                    if (kg + 1 > qg0) s[f][1] = -126.f;
                    if (kg     > qg1) s[f][2] = -126.f;
                    if (kg + 1 > qg1) s[f][3] = -126.f;
                }
            }

            uint32_t pah[2][4];
            #pragma unroll
            for (int ks2 = 0; ks2 < 2; ks2++) {
                #pragma unroll
                for (int ff = 0; ff < 2; ff++) {
                    const int f = ks2 * 2 + ff;
                    float p0 = fast_exp2(s[f][0]);
                    float p1 = fast_exp2(s[f][1]);
                    float p2 = fast_exp2(s[f][2]);
                    float p3 = fast_exp2(s[f][3]);
                    lsum0 += p0 + p1;
                    lsum1 += p2 + p3;
                    pah[ks2][ff * 2]     = pack2h(p0, p1);
                    pah[ks2][ff * 2 + 1] = pack2h(p2, p3);
                }
            }

            #pragma unroll
            for (int ks2 = 0; ks2 < 2; ks2++) {
                uint32_t vh[4][4];
                #pragma unroll
                for (int c = 0; c < 4; c++)
                    ldm_x4_t(vh[c], ldm_addr(sVH, kw * 32 + ks2 * 16, c * 16));
                #pragma unroll
                for (int j2 = 0; j2 < 8; j2++)
                    mma_f16(o[j2], pah[ks2], &vh[j2 >> 1][(j2 & 1) * 2]);
            }
        }
        __syncthreads();

        lsum0 += __shfl_xor_sync(0xFFFFFFFFu, lsum0, 1);
        lsum0 += __shfl_xor_sync(0xFFFFFFFFu, lsum0, 2);
        lsum1 += __shfl_xor_sync(0xFFFFFFFFu, lsum1, 1);
        lsum1 += __shfl_xor_sync(0xFFFFFFFFu, lsum1, 2);
        float* lred = reinterpret_cast<float*>(sm + ALR);
        if (t == 0) {
            lred[(qw * 2 + kw) * 16 + g]     = lsum0;
            lred[(qw * 2 + kw) * 16 + 8 + g] = lsum1;
        }
        float* ored = reinterpret_cast<float*>(sm);
        if (kw == 1) {
            #pragma unroll
            for (int j2 = 0; j2 < 8; j2++) {
                int col = j2 * 8 + t * 2;
                *reinterpret_cast<float2*>(&ored[(qw * 16 + g) * 64 + col]) =
                    make_float2(o[j2][0], o[j2][1]);
                *reinterpret_cast<float2*>(&ored[(qw * 16 + g + 8) * 64 + col]) =
                    make_float2(o[j2][2], o[j2][3]);
            }
        }
        __syncthreads();

        if (kw == 0) {
            float inv0 = 1.f / (lred[(qw * 2) * 16 + g]     + lred[(qw * 2 + 1) * 16 + g]);
            float inv1 = 1.f / (lred[(qw * 2) * 16 + 8 + g] + lred[(qw * 2 + 1) * 16 + 8 + g]);
            #pragma unroll
            for (int j2 = 0; j2 < 8; j2++) {
                int col = j2 * 8 + t * 2;
                float2 a0 = *reinterpret_cast<float2*>(&ored[(qw * 16 + g) * 64 + col]);
                float2 a1 = *reinterpret_cast<float2*>(&ored[(qw * 16 + g + 8) * 64 + col]);
                size_t r0 = (base + q0c + qw * 16 + g) * HH + col;
                *reinterpret_cast<float2*>(Outp + r0) =
                    make_float2((o[j2][0] + a0.x) * inv0, (o[j2][1] + a0.y) * inv0);
                *reinterpret_cast<float2*>(Outp + r0 + 8 * HH) =
                    make_float2((o[j2][2] + a1.x) * inv1, (o[j2][3] + a1.y) * inv1);
            }
        }
    }
}

// ---------------------------------------------------------------------------
extern "C" void kernel_launch(void* const* d_in, const int* in_sizes, int n_in,
                              void* d_out, int out_size)
{
    const float* X  = (const float*)d_in[0];
    const float* Wk = (const float*)d_in[1];
    const float* Wq = (const float*)d_in[2];
    const float* Wv = (const float*)d_in[3];
    float* Out = (float*)d_out;
    (void)in_sizes; (void)n_in; (void)out_size;

    cudaFuncSetAttribute(fused_head, cudaFuncAttributeMaxDynamicSharedMemorySize, ATOT);
    fused_head<<<GRID, 128, ATOT>>>(X, Wq, Wk, Wv, Out);
}

// round 15
// speedup vs baseline: 1.2161x; 1.2161x over previous
#include <cuda_runtime.h>
#include <cuda_fp16.h>
#include <cstdint>

#define BB 8
#define SS 2048
#define DD 1024
#define HH 64
#define MM (BB*SS)
#define PGRID 256

// Scratch (fp16): Q pre-scaled by log2e/32; K,V hi-only
__device__ __align__(16) __half g_Qh[MM*HH];
__device__ __align__(16) __half g_Kh[MM*HH];
__device__ __align__(16) __half g_Vh[MM*HH];
// W hi (fp16 rn): [3][64][1024], mat order {Q,K,V}
__device__ __align__(16) __half g_Wh[3*HH*DD];
// grid barrier ticket counter (monotonic; stays PGRID-aligned across replays)
__device__ unsigned g_bar;

// ---------------------------------------------------------------------------
// helpers
// ---------------------------------------------------------------------------
__device__ __forceinline__ uint32_t pack2h(float lo, float hi) {
    uint32_t r;
    asm("cvt.rn.f16x2.f32 %0, %1, %2;" : "=r"(r) : "f"(hi), "f"(lo));
    return r;
}

__device__ __forceinline__ void ldm_x4(uint32_t* r, uint32_t addr) {
    asm volatile("ldmatrix.sync.aligned.m8n8.x4.shared.b16 {%0,%1,%2,%3}, [%4];"
                 : "=r"(r[0]), "=r"(r[1]), "=r"(r[2]), "=r"(r[3]) : "r"(addr));
}
__device__ __forceinline__ void ldm_x4_t(uint32_t* r, uint32_t addr) {
    asm volatile("ldmatrix.sync.aligned.m8n8.x4.trans.shared.b16 {%0,%1,%2,%3}, [%4];"
                 : "=r"(r[0]), "=r"(r[1]), "=r"(r[2]), "=r"(r[3]) : "r"(addr));
}

__device__ __forceinline__ void cp16(uint32_t dst, const void* src) {
    asm volatile("cp.async.cg.shared.global [%0], [%1], 16;"
                 :: "r"(dst), "l"(src) : "memory");
}
#define CP_COMMIT() asm volatile("cp.async.commit_group;" ::: "memory")
#define CP_WAIT0()  asm volatile("cp.async.wait_group 0;" ::: "memory")

// smem fp16 tiles: row stride 144 bytes (72 halves) -> ldmatrix conflict-free
#define LDB 144

__device__ __forceinline__ uint32_t ldm_addr(uint32_t base, int row0, int col0) {
    int l = threadIdx.x & 31;
    int r = row0 + (l & 7) + ((l >> 3) & 1) * 8;
    int c = col0 + (l >> 4) * 8;
    return base + r * LDB + c * 2;
}
__device__ __forceinline__ uint32_t ldm_addr_b(uint32_t base, int row0, int col0) {
    int l = threadIdx.x & 31;
    int r = row0 + (l & 7) + (l >> 4) * 8;
    int c = col0 + ((l >> 3) & 1) * 8;
    return base + r * LDB + c * 2;
}

__device__ __forceinline__ void mma_f16(float* d, const uint32_t* a, const uint32_t* b) {
    asm volatile(
        "mma.sync.aligned.m16n8k16.row.col.f32.f16.f16.f32 "
        "{%0,%1,%2,%3}, {%4,%5,%6,%7}, {%8,%9}, {%0,%1,%2,%3};"
        : "+f"(d[0]), "+f"(d[1]), "+f"(d[2]), "+f"(d[3])
        : "r"(a[0]), "r"(a[1]), "r"(a[2]), "r"(a[3]), "r"(b[0]), "r"(b[1]));
}

// 2^x via magic-round + deg-4 Taylor. No clamp: inputs bounded (masked = -126).
__device__ __forceinline__ float fast_exp2(float x) {
    float r = x + 12582912.0f;
    int ik = __float_as_int(r) - 0x4B400000;
    float f = x - (r - 12582912.0f);
    float p = fmaf(0.0096180f, f, 0.0555041f);
    p = fmaf(p, f, 0.2402265f);
    p = fmaf(p, f, 0.6931472f);
    p = fmaf(p, f, 1.0f);
    return __int_as_float(__float_as_int(p) + (ik << 23));
}

// Grid-wide barrier for proj_tc (PGRID CTAs, single wave -> spin-safe).
__device__ __forceinline__ void grid_barrier() {
    __syncthreads();
    __threadfence();
    if (threadIdx.x == 0) {
        unsigned tck = atomicAdd(&g_bar, 1u);
        unsigned rel = (tck / PGRID + 1u) * PGRID;
        unsigned v;
        do {
            asm volatile("ld.volatile.global.u32 %0, [%1];"
                         : "=r"(v) : "l"(&g_bar) : "memory");
        } while (v < rel);
        __threadfence();
    }
    __syncthreads();
}

// ---------------------------------------------------------------------------
// proj: phase A converts W f32->f16 (grid-strided), grid barrier, then
// Q,K,V = Xh @ Wh^T (1-term fp16). CTA = 64 rows, 256 thr, 256 CTAs (occ 2,
// single wave). Warps 2m x 4n. Outputs fp16 hi-only (Q scaled by log2e/32).
// ---------------------------------------------------------------------------
#define PTM 64
#define PXH 0
#define PWH 9216
#define PTOT 36864

__global__ __launch_bounds__(256, 2) void proj_tc(const float* __restrict__ X,
                                                  const float* __restrict__ Wq,
                                                  const float* __restrict__ Wk,
                                                  const float* __restrict__ Wv) {
    extern __shared__ char sm[];
    const uint32_t sb = (uint32_t)__cvta_generic_to_shared(sm);
    const int tid = threadIdx.x, wid = tid >> 5, lane = tid & 31;
    const int g = lane >> 2, t = lane & 3;
    const int wm = wid >> 2, wn = wid & 3;
    const int m0 = blockIdx.x * PTM;

    // ---------------- Phase A: W f32 -> f16 (rn), bit-identical to prep_w ---
    {
        int gid = blockIdx.x * 256 + tid;   // 65536 threads, 49152 float4 jobs
        if (gid < 3 * 16384) {
            int mat = gid >> 14;
            int idx4 = gid & 16383;
            const float* W = (mat == 0) ? Wq : ((mat == 1) ? Wk : Wv);
            float4 v = reinterpret_cast<const float4*>(W)[idx4];
            uint32_t* ph = reinterpret_cast<uint32_t*>(g_Wh);
            ph[mat * 32768 + idx4 * 2]     = pack2h(v.x, v.y);
            ph[mat * 32768 + idx4 * 2 + 1] = pack2h(v.z, v.w);
        }
    }
    grid_barrier();

    // ---------------- Phase B: projection (identical to round 13) ----------
    float acc[3][2][2][4];
    #pragma unroll
    for (int a = 0; a < 3; a++)
        #pragma unroll
        for (int b = 0; b < 2; b++)
            #pragma unroll
            for (int c = 0; c < 2; c++)
                #pragma unroll
                for (int d = 0; d < 4; d++) acc[a][b][c][d] = 0.f;

    for (int kc = 0; kc < 16; kc++) {
        const int kbase = kc * 64;
        #pragma unroll
        for (int i = 0; i < 4; i++) {
            int id = tid + i * 256;
            int row = id >> 4, c4 = id & 15;
            float4 v = *reinterpret_cast<const float4*>(
                X + (size_t)(m0 + row) * DD + kbase + c4 * 4);
            uint32_t off = row * LDB + c4 * 8;
            *reinterpret_cast<uint32_t*>(sm + PXH + off)     = pack2h(v.x, v.y);
            *reinterpret_cast<uint32_t*>(sm + PXH + off + 4) = pack2h(v.z, v.w);
        }
        #pragma unroll
        for (int i = 0; i < 6; i++) {
            int id = tid + i * 256;
            int row = id >> 3, c = id & 7;
            uint4 v = *reinterpret_cast<const uint4*>(g_Wh + (size_t)row * DD + kbase + c * 8);
            *reinterpret_cast<uint4*>(sm + PWH + row * LDB + c * 16) = v;
        }
        __syncthreads();

        #pragma unroll
        for (int ks = 0; ks < 4; ks++) {
            uint32_t ah[2][4];
            #pragma unroll
            for (int fm = 0; fm < 2; fm++)
                ldm_x4(ah[fm], ldm_addr(sb + PXH, wm * 32 + fm * 16, ks * 16));
            #pragma unroll
            for (int mat = 0; mat < 3; mat++) {
                uint32_t bh[4];
                ldm_x4(bh, ldm_addr_b(sb + PWH, mat * 64 + wn * 16, ks * 16));
                #pragma unroll
                for (int fm = 0; fm < 2; fm++)
                    #pragma unroll
                    for (int fn = 0; fn < 2; fn++)
                        mma_f16(acc[mat][fm][fn], ah[fm], &bh[fn * 2]);
            }
        }
        __syncthreads();
    }

    #pragma unroll
    for (int mat = 0; mat < 3; mat++) {
        __half* gh = (mat == 0) ? g_Qh : ((mat == 1) ? g_Kh : g_Vh);
        const float scl = (mat == 0) ? (1.44269504f / 32.0f) : 1.0f;
        #pragma unroll
        for (int fm = 0; fm < 2; fm++)
            #pragma unroll
            for (int fn = 0; fn < 2; fn++) {
                const float* c = acc[mat][fm][fn];
                int r0 = m0 + wm * 32 + fm * 16 + g;
                int col = wn * 16 + fn * 8 + t * 2;
                reinterpret_cast<uint32_t*>(gh)[((size_t)r0 * HH + col) >> 1] =
                    pack2h(c[0] * scl, c[1] * scl);
                reinterpret_cast<uint32_t*>(gh)[((size_t)(r0 + 8) * HH + col) >> 1] =
                    pack2h(c[2] * scl, c[3] * scl);
            }
    }
}

// ---------------------------------------------------------------------------
// attn: flash attention (fp16 hi-only), no-max softmax, register P, hoisted Q.
// CTA = 32 query rows, 128 threads (warps 2 qw x 2 kw), grid 512 = single
// wave at occ 4. LPT snake schedule. Identical to round 13.
// ---------------------------------------------------------------------------
#define AQ    0
#define ABUF  4608
#define PLANE 9216
#define STG   (2 * PLANE)
#define ALR   (ABUF + 2 * STG)  // 41472
#define ATOT  (ALR + 256)       // 41728

__global__ __launch_bounds__(128, 4) void attn_tc(float* __restrict__ Outp) {
    extern __shared__ char sm[];
    const uint32_t sb = (uint32_t)__cvta_generic_to_shared(sm);
    const int tid = threadIdx.x, wid = tid >> 5, lane = tid & 31;
    const int g = lane >> 2, t = lane & 3;
    const int qw = wid >> 1, kw = wid & 1;

    const int bid = blockIdx.x;
    int r = bid / 148, j = bid - r * 148;
    int i = (r < 3) ? (r * 148 + ((r & 1) ? (147 - j) : j)) : bid;
    const int qt = 31 - (i >> 4);
    const int sub = i & 15;
    const int b = sub >> 1, half = sub & 1;

    const int q0c = qt * 64 + half * 32;
    const size_t base = (size_t)b * SS;

    #pragma unroll
    for (int i2 = 0; i2 < 8; i2++) {
        int id = tid + i2 * 128;
        int plane = id >> 9, rem = id & 511;
        int row = rem >> 3, c = rem & 7;
        const __half* src = (plane == 0) ? g_Kh : g_Vh;
        cp16(sb + ABUF + plane * PLANE + row * LDB + c * 16,
             src + (base + row) * HH + c * 8);
    }
    CP_COMMIT();

    #pragma unroll
    for (int i2 = 0; i2 < 2; i2++) {
        int id = tid + i2 * 128;
        int row = id >> 3, c = id & 7;
        *reinterpret_cast<uint4*>(sm + AQ + row * LDB + c * 16) =
            *reinterpret_cast<const uint4*>(g_Qh + (base + q0c + row) * HH + c * 8);
    }
    __syncthreads();
    uint32_t qa[4][4];
    #pragma unroll
    for (int hs = 0; hs < 4; hs++)
        ldm_x4(qa[hs], ldm_addr(sb + AQ, qw * 16, hs * 16));

    float o[8][4];
    #pragma unroll
    for (int i2 = 0; i2 < 8; i2++)
        #pragma unroll
        for (int j2 = 0; j2 < 4; j2++) o[i2][j2] = 0.f;
    float lsum0 = 0.f, lsum1 = 0.f;

    for (int kt = 0; kt <= qt; kt++) {
        const int k0 = kt * 64;
        CP_WAIT0();
        __syncthreads();

        if (kt < qt) {
            const int kn = k0 + 64;
            const uint32_t dstg = sb + ABUF + ((kt + 1) & 1) * STG;
            #pragma unroll
            for (int i2 = 0; i2 < 8; i2++) {
                int id = tid + i2 * 128;
                int plane = id >> 9, rem = id & 511;
                int row = rem >> 3, c = rem & 7;
                const __half* src = (plane == 0) ? g_Kh : g_Vh;
                cp16(dstg + plane * PLANE + row * LDB + c * 16,
                     src + (base + kn + row) * HH + c * 8);
            }
        }
        CP_COMMIT();

        if (kt == qt && half == 0 && kw == 1) continue;

        const uint32_t stg = sb + ABUF + (kt & 1) * STG;
        const uint32_t sKH = stg, sVH = stg + PLANE;

        float s[4][4];
        #pragma unroll
        for (int i2 = 0; i2 < 4; i2++)
            #pragma unroll
            for (int j2 = 0; j2 < 4; j2++) s[i2][j2] = 0.f;

        #pragma unroll
        for (int hs = 0; hs < 4; hs++) {
            uint32_t bh[4], bh2[4];
            ldm_x4(bh,  ldm_addr_b(sKH, kw * 32,      hs * 16));
            ldm_x4(bh2, ldm_addr_b(sKH, kw * 32 + 16, hs * 16));
            #pragma unroll
            for (int fn = 0; fn < 2; fn++) {
                mma_f16(s[fn],     qa[hs], &bh[fn * 2]);
                mma_f16(s[2 + fn], qa[hs], &bh2[fn * 2]);
            }
        }

        if (kt == qt) {
            #pragma unroll
            for (int f = 0; f < 4; f++) {
                int kg = k0 + kw * 32 + f * 8 + t * 2;
                int qg0 = q0c + qw * 16 + g, qg1 = qg0 + 8;
                if (kg     > qg0) s[f][0] = -126.f;
                if (kg + 1 > qg0) s[f][1] = -126.f;
                if (kg     > qg1) s[f][2] = -126.f;
                if (kg + 1 > qg1) s[f][3] = -126.f;
            }
        }

        uint32_t pah[2][4];
        #pragma unroll
        for (int ks2 = 0; ks2 < 2; ks2++) {
            #pragma unroll
            for (int ff = 0; ff < 2; ff++) {
                const int f = ks2 * 2 + ff;
                float p0 = fast_exp2(s[f][0]);
                float p1 = fast_exp2(s[f][1]);
                float p2 = fast_exp2(s[f][2]);
                float p3 = fast_exp2(s[f][3]);
                lsum0 += p0 + p1;
                lsum1 += p2 + p3;
                pah[ks2][ff * 2]     = pack2h(p0, p1);
                pah[ks2][ff * 2 + 1] = pack2h(p2, p3);
            }
        }

        #pragma unroll
        for (int ks2 = 0; ks2 < 2; ks2++) {
            uint32_t vh[4][4];
            #pragma unroll
            for (int c = 0; c < 4; c++)
                ldm_x4_t(vh[c], ldm_addr(sVH, kw * 32 + ks2 * 16, c * 16));
            #pragma unroll
            for (int j2 = 0; j2 < 8; j2++)
                mma_f16(o[j2], pah[ks2], &vh[j2 >> 1][(j2 & 1) * 2]);
        }
    }
    __syncthreads();

    lsum0 += __shfl_xor_sync(0xFFFFFFFFu, lsum0, 1);
    lsum0 += __shfl_xor_sync(0xFFFFFFFFu, lsum0, 2);
    lsum1 += __shfl_xor_sync(0xFFFFFFFFu, lsum1, 1);
    lsum1 += __shfl_xor_sync(0xFFFFFFFFu, lsum1, 2);
    float* lred = reinterpret_cast<float*>(sm + ALR);
    if (t == 0) {
        lred[(qw * 2 + kw) * 16 + g]     = lsum0;
        lred[(qw * 2 + kw) * 16 + 8 + g] = lsum1;
    }
    float* ored = reinterpret_cast<float*>(sm);
    if (kw == 1) {
        #pragma unroll
        for (int j2 = 0; j2 < 8; j2++) {
            int col = j2 * 8 + t * 2;
            *reinterpret_cast<float2*>(&ored[(qw * 16 + g) * 64 + col]) =
                make_float2(o[j2][0], o[j2][1]);
            *reinterpret_cast<float2*>(&ored[(qw * 16 + g + 8) * 64 + col]) =
                make_float2(o[j2][2], o[j2][3]);
        }
    }
    __syncthreads();

    if (kw == 0) {
        float inv0 = 1.f / (lred[(qw * 2) * 16 + g]     + lred[(qw * 2 + 1) * 16 + g]);
        float inv1 = 1.f / (lred[(qw * 2) * 16 + 8 + g] + lred[(qw * 2 + 1) * 16 + 8 + g]);
        #pragma unroll
        for (int j2 = 0; j2 < 8; j2++) {
            int col = j2 * 8 + t * 2;
            float2 a0 = *reinterpret_cast<float2*>(&ored[(qw * 16 + g) * 64 + col]);
            float2 a1 = *reinterpret_cast<float2*>(&ored[(qw * 16 + g + 8) * 64 + col]);
            size_t r0 = (base + q0c + qw * 16 + g) * HH + col;
            *reinterpret_cast<float2*>(Outp + r0) =
                make_float2((o[j2][0] + a0.x) * inv0, (o[j2][1] + a0.y) * inv0);
            *reinterpret_cast<float2*>(Outp + r0 + 8 * HH) =
                make_float2((o[j2][2] + a1.x) * inv1, (o[j2][3] + a1.y) * inv1);
        }
    }
}

// ---------------------------------------------------------------------------
extern "C" void kernel_launch(void* const* d_in, const int* in_sizes, int n_in,
                              void* d_out, int out_size)
{
    const float* X  = (const float*)d_in[0];
    const float* Wk = (const float*)d_in[1];
    const float* Wq = (const float*)d_in[2];
    const float* Wv = (const float*)d_in[3];
    float* Out = (float*)d_out;
    (void)in_sizes; (void)n_in; (void)out_size;

    cudaFuncSetAttribute(proj_tc, cudaFuncAttributeMaxDynamicSharedMemorySize, PTOT);
    cudaFuncSetAttribute(attn_tc, cudaFuncAttributeMaxDynamicSharedMemorySize, ATOT);

    proj_tc<<<PGRID, 256, PTOT>>>(X, Wq, Wk, Wv);
    attn_tc<<<512, 128, ATOT>>>(Out);
}

// round 16
// speedup vs baseline: 1.3045x; 1.0726x over previous
#include <cuda_runtime.h>
#include <cuda_fp16.h>
#include <cstdint>

#define BB 8
#define SS 2048
#define DD 1024
#define HH 64
#define MM (BB*SS)
#define GRID 256

// Scratch (fp16): Q pre-scaled by log2e/32; K,V hi-only
__device__ __align__(16) __half g_Qh[MM*HH];
__device__ __align__(16) __half g_Kh[MM*HH];
__device__ __align__(16) __half g_Vh[MM*HH];
// W hi (fp16 rn): [3][64][1024], mat order {Q,K,V}
__device__ __align__(16) __half g_Wh[3*HH*DD];
// grid barrier ticket counter (monotonic; stays GRID-aligned across replays)
__device__ unsigned g_bar;

// ---------------------------------------------------------------------------
// helpers
// ---------------------------------------------------------------------------
__device__ __forceinline__ uint32_t pack2h(float lo, float hi) {
    uint32_t r;
    asm("cvt.rn.f16x2.f32 %0, %1, %2;" : "=r"(r) : "f"(hi), "f"(lo));
    return r;
}

__device__ __forceinline__ void ldm_x4(uint32_t* r, uint32_t addr) {
    asm volatile("ldmatrix.sync.aligned.m8n8.x4.shared.b16 {%0,%1,%2,%3}, [%4];"
                 : "=r"(r[0]), "=r"(r[1]), "=r"(r[2]), "=r"(r[3]) : "r"(addr));
}
__device__ __forceinline__ void ldm_x4_t(uint32_t* r, uint32_t addr) {
    asm volatile("ldmatrix.sync.aligned.m8n8.x4.trans.shared.b16 {%0,%1,%2,%3}, [%4];"
                 : "=r"(r[0]), "=r"(r[1]), "=r"(r[2]), "=r"(r[3]) : "r"(addr));
}

__device__ __forceinline__ void cp16(uint32_t dst, const void* src) {
    asm volatile("cp.async.cg.shared.global [%0], [%1], 16;"
                 :: "r"(dst), "l"(src) : "memory");
}
#define CP_COMMIT() asm volatile("cp.async.commit_group;" ::: "memory")
#define CP_WAIT0()  asm volatile("cp.async.wait_group 0;" ::: "memory")

// named barrier for a 128-thread half-CTA (ids 1 and 2; 0 left for syncthreads)
#define NBAR(idb) asm volatile("bar.sync %0, 128;" :: "r"(idb) : "memory")

// smem fp16 tiles: row stride 144 bytes (72 halves) -> ldmatrix conflict-free
#define LDB 144

__device__ __forceinline__ uint32_t ldm_addr(uint32_t base, int row0, int col0) {
    int l = threadIdx.x & 31;
    int r = row0 + (l & 7) + ((l >> 3) & 1) * 8;
    int c = col0 + (l >> 4) * 8;
    return base + r * LDB + c * 2;
}
__device__ __forceinline__ uint32_t ldm_addr_b(uint32_t base, int row0, int col0) {
    int l = threadIdx.x & 31;
    int r = row0 + (l & 7) + (l >> 4) * 8;
    int c = col0 + ((l >> 3) & 1) * 8;
    return base + r * LDB + c * 2;
}

__device__ __forceinline__ void mma_f16(float* d, const uint32_t* a, const uint32_t* b) {
    asm volatile(
        "mma.sync.aligned.m16n8k16.row.col.f32.f16.f16.f32 "
        "{%0,%1,%2,%3}, {%4,%5,%6,%7}, {%8,%9}, {%0,%1,%2,%3};"
        : "+f"(d[0]), "+f"(d[1]), "+f"(d[2]), "+f"(d[3])
        : "r"(a[0]), "r"(a[1]), "r"(a[2]), "r"(a[3]), "r"(b[0]), "r"(b[1]));
}

// 2^x via magic-round + deg-4 Taylor. No clamp: inputs bounded (masked = -126).
__device__ __forceinline__ float fast_exp2(float x) {
    float r = x + 12582912.0f;
    int ik = __float_as_int(r) - 0x4B400000;
    float f = x - (r - 12582912.0f);
    float p = fmaf(0.0096180f, f, 0.0555041f);
    p = fmaf(p, f, 0.2402265f);
    p = fmaf(p, f, 0.6931472f);
    p = fmaf(p, f, 1.0f);
    return __int_as_float(__float_as_int(p) + (ik << 23));
}

// Grid-wide barrier (GRID CTAs, single wave -> spin-safe).
__device__ __forceinline__ void grid_barrier() {
    __syncthreads();
    __threadfence();
    if (threadIdx.x == 0) {
        unsigned tck = atomicAdd(&g_bar, 1u);
        unsigned rel = (tck / GRID + 1u) * GRID;
        unsigned v;
        do {
            asm volatile("ld.volatile.global.u32 %0, [%1];"
                         : "=r"(v) : "l"(&g_bar) : "memory");
        } while (v < rel);
        __threadfence();
    }
    __syncthreads();
}

// ---------------------------------------------------------------------------
// smem layout
// proj phase: X at 0 (64*144=9216), W at 9216 (+192*144=27648) -> 36864
// attn phase: two independent 41728-byte half slices (Q 4608 + K/V 2x18432 + lred)
// ---------------------------------------------------------------------------
#define PXH   0
#define PWH   9216
#define AQ    0
#define ABUF  4608
#define PLANE 9216
#define STG   (2 * PLANE)
#define ALR   (ABUF + 2 * STG)   // 41472 (within half slice)
#define HSZ   41728              // half slice size
#define TOT   (2 * HSZ)          // 83456

__global__ __launch_bounds__(256, 2) void fused_head(
    const float* __restrict__ X,
    const float* __restrict__ Wq,
    const float* __restrict__ Wk,
    const float* __restrict__ Wv,
    float* __restrict__ Outp)
{
    extern __shared__ char sm[];
    const int tid = threadIdx.x;
    const int bid = blockIdx.x;

    // ======================= Phase A: W f32 -> f16 =========================
    {
        int gid = bid * 256 + tid;          // 65536 threads, 49152 float4 jobs
        if (gid < 3 * 16384) {
            int mat = gid >> 14;
            int idx4 = gid & 16383;
            const float* W = (mat == 0) ? Wq : ((mat == 1) ? Wk : Wv);
            float4 v = reinterpret_cast<const float4*>(W)[idx4];
            uint32_t* ph = reinterpret_cast<uint32_t*>(g_Wh);
            ph[mat * 32768 + idx4 * 2]     = pack2h(v.x, v.y);
            ph[mat * 32768 + idx4 * 2 + 1] = pack2h(v.z, v.w);
        }
    }
    grid_barrier();

    // ======================= Phase B: projection (R13 body) ================
    {
        const uint32_t sb = (uint32_t)__cvta_generic_to_shared(sm);
        const int wid = tid >> 5, lane = tid & 31;
        const int g = lane >> 2, t = lane & 3;
        const int wm = wid >> 2, wn = wid & 3;
        const int m0 = bid * 64;

        float acc[3][2][2][4];
        #pragma unroll
        for (int a = 0; a < 3; a++)
            #pragma unroll
            for (int b = 0; b < 2; b++)
                #pragma unroll
                for (int c = 0; c < 2; c++)
                    #pragma unroll
                    for (int d = 0; d < 4; d++) acc[a][b][c][d] = 0.f;

        for (int kc = 0; kc < 16; kc++) {
            const int kbase = kc * 64;
            #pragma unroll
            for (int i = 0; i < 4; i++) {
                int id = tid + i * 256;
                int row = id >> 4, c4 = id & 15;
                float4 v = *reinterpret_cast<const float4*>(
                    X + (size_t)(m0 + row) * DD + kbase + c4 * 4);
                uint32_t off = row * LDB + c4 * 8;
                *reinterpret_cast<uint32_t*>(sm + PXH + off)     = pack2h(v.x, v.y);
                *reinterpret_cast<uint32_t*>(sm + PXH + off + 4) = pack2h(v.z, v.w);
            }
            #pragma unroll
            for (int i = 0; i < 6; i++) {
                int id = tid + i * 256;
                int row = id >> 3, c = id & 7;
                uint4 v = *reinterpret_cast<const uint4*>(
                    g_Wh + (size_t)row * DD + kbase + c * 8);
                *reinterpret_cast<uint4*>(sm + PWH + row * LDB + c * 16) = v;
            }
            __syncthreads();

            #pragma unroll
            for (int ks = 0; ks < 4; ks++) {
                uint32_t ah[2][4];
                #pragma unroll
                for (int fm = 0; fm < 2; fm++)
                    ldm_x4(ah[fm], ldm_addr(sb + PXH, wm * 32 + fm * 16, ks * 16));
                #pragma unroll
                for (int mat = 0; mat < 3; mat++) {
                    uint32_t bh[4];
                    ldm_x4(bh, ldm_addr_b(sb + PWH, mat * 64 + wn * 16, ks * 16));
                    #pragma unroll
                    for (int fm = 0; fm < 2; fm++)
                        #pragma unroll
                        for (int fn = 0; fn < 2; fn++)
                            mma_f16(acc[mat][fm][fn], ah[fm], &bh[fn * 2]);
                }
            }
            __syncthreads();
        }

        #pragma unroll
        for (int mat = 0; mat < 3; mat++) {
            __half* gh = (mat == 0) ? g_Qh : ((mat == 1) ? g_Kh : g_Vh);
            const float scl = (mat == 0) ? (1.44269504f / 32.0f) : 1.0f;
            #pragma unroll
            for (int fm = 0; fm < 2; fm++)
                #pragma unroll
                for (int fn = 0; fn < 2; fn++) {
                    const float* c = acc[mat][fm][fn];
                    int r0 = m0 + wm * 32 + fm * 16 + g;
                    int col = wn * 16 + fn * 8 + t * 2;
                    reinterpret_cast<uint32_t*>(gh)[((size_t)r0 * HH + col) >> 1] =
                        pack2h(c[0] * scl, c[1] * scl);
                    reinterpret_cast<uint32_t*>(gh)[((size_t)(r0 + 8) * HH + col) >> 1] =
                        pack2h(c[2] * scl, c[3] * scl);
                }
        }
    }
    grid_barrier();

    // ======================= Phase C: attention ============================
    // Two independent 128-thread halves per CTA, each = one R13 attn CTA.
    {
        const int h = tid >> 7;              // half id 0/1
        const int t128 = tid & 127;
        char* smh = sm + h * HSZ;
        const uint32_t sbh = (uint32_t)__cvta_generic_to_shared(smh);
        const int wid = t128 >> 5, lane = t128 & 31;
        const int g = lane >> 2, t = lane & 3;
        const int qw = wid >> 1, kw = wid & 1;
        const int nbid = 1 + h;

        // job mapping: solo SMs (bids 108..147) get pairs summing ~42;
        // dual SMs get snake-balanced quadruples (~60).
        int jb;
        if (bid >= 108 && bid < 148) {
            int c = bid - 108;
            jb = h ? (335 - c) : (32 + c);
        } else {
            int s2 = (bid < 108) ? bid : (bid - 148);
            int pos = (bid < 108) ? (h ? (215 - s2) : s2)
                                  : (h ? (431 - s2) : (216 + s2));
            jb = (pos < 32) ? pos : ((pos < 256) ? pos + 40 : pos + 80);
        }
        const int qt = 31 - (jb >> 4);
        const int sub = jb & 15;
        const int b = sub >> 1, half = sub & 1;

        const int q0c = qt * 64 + half * 32;
        const size_t base = (size_t)b * SS;

        // prefetch K/V tile 0
        #pragma unroll
        for (int i2 = 0; i2 < 8; i2++) {
            int id = t128 + i2 * 128;
            int plane = id >> 9, rem = id & 511;
            int row = rem >> 3, c = rem & 7;
            const __half* src = (plane == 0) ? g_Kh : g_Vh;
            cp16(sbh + ABUF + plane * PLANE + row * LDB + c * 16,
                 src + (base + row) * HH + c * 8);
        }
        CP_COMMIT();

        // load Q tile (32 rows), hoist this warp's fragments
        #pragma unroll
        for (int i2 = 0; i2 < 2; i2++) {
            int id = t128 + i2 * 128;
            int row = id >> 3, c = id & 7;
            *reinterpret_cast<uint4*>(smh + AQ + row * LDB + c * 16) =
                *reinterpret_cast<const uint4*>(g_Qh + (base + q0c + row) * HH + c * 8);
        }
        NBAR(nbid);
        uint32_t qa[4][4];
        #pragma unroll
        for (int hs = 0; hs < 4; hs++)
            ldm_x4(qa[hs], ldm_addr(sbh + AQ, qw * 16, hs * 16));

        float o[8][4];
        #pragma unroll
        for (int i2 = 0; i2 < 8; i2++)
            #pragma unroll
            for (int j2 = 0; j2 < 4; j2++) o[i2][j2] = 0.f;
        float lsum0 = 0.f, lsum1 = 0.f;

        for (int kt = 0; kt <= qt; kt++) {
            const int k0 = kt * 64;
            CP_WAIT0();
            NBAR(nbid);

            if (kt < qt) {
                const int kn = k0 + 64;
                const uint32_t dstg = sbh + ABUF + ((kt + 1) & 1) * STG;
                #pragma unroll
                for (int i2 = 0; i2 < 8; i2++) {
                    int id = t128 + i2 * 128;
                    int plane = id >> 9, rem = id & 511;
                    int row = rem >> 3, c = rem & 7;
                    const __half* src = (plane == 0) ? g_Kh : g_Vh;
                    cp16(dstg + plane * PLANE + row * LDB + c * 16,
                         src + (base + kn + row) * HH + c * 8);
                }
            }
            CP_COMMIT();

            if (kt == qt && half == 0 && kw == 1) continue;

            const uint32_t stg = sbh + ABUF + (kt & 1) * STG;
            const uint32_t sKH = stg, sVH = stg + PLANE;

            float s[4][4];
            #pragma unroll
            for (int i2 = 0; i2 < 4; i2++)
                #pragma unroll
                for (int j2 = 0; j2 < 4; j2++) s[i2][j2] = 0.f;

            #pragma unroll
            for (int hs = 0; hs < 4; hs++) {
                uint32_t bh[4], bh2[4];
                ldm_x4(bh,  ldm_addr_b(sKH, kw * 32,      hs * 16));
                ldm_x4(bh2, ldm_addr_b(sKH, kw * 32 + 16, hs * 16));
                #pragma unroll
                for (int fn = 0; fn < 2; fn++) {
                    mma_f16(s[fn],     qa[hs], &bh[fn * 2]);
                    mma_f16(s[2 + fn], qa[hs], &bh2[fn * 2]);
                }
            }

            if (kt == qt) {
                #pragma unroll
                for (int f = 0; f < 4; f++) {
                    int kg = k0 + kw * 32 + f * 8 + t * 2;
                    int qg0 = q0c + qw * 16 + g, qg1 = qg0 + 8;
                    if (kg     > qg0) s[f][0] = -126.f;
                    if (kg + 1 > qg0) s[f][1] = -126.f;
                    if (kg     > qg1) s[f][2] = -126.f;
                    if (kg + 1 > qg1) s[f][3] = -126.f;
                }
            }

            uint32_t pah[2][4];
            #pragma unroll
            for (int ks2 = 0; ks2 < 2; ks2++) {
                #pragma unroll
                for (int ff = 0; ff < 2; ff++) {
                    const int f = ks2 * 2 + ff;
                    float p0 = fast_exp2(s[f][0]);
                    float p1 = fast_exp2(s[f][1]);
                    float p2 = fast_exp2(s[f][2]);
                    float p3 = fast_exp2(s[f][3]);
                    lsum0 += p0 + p1;
                    lsum1 += p2 + p3;
                    pah[ks2][ff * 2]     = pack2h(p0, p1);
                    pah[ks2][ff * 2 + 1] = pack2h(p2, p3);
                }
            }

            #pragma unroll
            for (int ks2 = 0; ks2 < 2; ks2++) {
                uint32_t vh[4][4];
                #pragma unroll
                for (int c = 0; c < 4; c++)
                    ldm_x4_t(vh[c], ldm_addr(sVH, kw * 32 + ks2 * 16, c * 16));
                #pragma unroll
                for (int j2 = 0; j2 < 8; j2++)
                    mma_f16(o[j2], pah[ks2], &vh[j2 >> 1][(j2 & 1) * 2]);
            }
        }
        NBAR(nbid);

        lsum0 += __shfl_xor_sync(0xFFFFFFFFu, lsum0, 1);
        lsum0 += __shfl_xor_sync(0xFFFFFFFFu, lsum0, 2);
        lsum1 += __shfl_xor_sync(0xFFFFFFFFu, lsum1, 1);
        lsum1 += __shfl_xor_sync(0xFFFFFFFFu, lsum1, 2);
        float* lred = reinterpret_cast<float*>(smh + ALR);
        if (t == 0) {
            lred[(qw * 2 + kw) * 16 + g]     = lsum0;
            lred[(qw * 2 + kw) * 16 + 8 + g] = lsum1;
        }
        float* ored = reinterpret_cast<float*>(smh);
        if (kw == 1) {
            #pragma unroll
            for (int j2 = 0; j2 < 8; j2++) {
                int col = j2 * 8 + t * 2;
                *reinterpret_cast<float2*>(&ored[(qw * 16 + g) * 64 + col]) =
                    make_float2(o[j2][0], o[j2][1]);
                *reinterpret_cast<float2*>(&ored[(qw * 16 + g + 8) * 64 + col]) =
                    make_float2(o[j2][2], o[j2][3]);
            }
        }
        NBAR(nbid);

        if (kw == 0) {
            float inv0 = 1.f / (lred[(qw * 2) * 16 + g]     + lred[(qw * 2 + 1) * 16 + g]);
            float inv1 = 1.f / (lred[(qw * 2) * 16 + 8 + g] + lred[(qw * 2 + 1) * 16 + 8 + g]);
            #pragma unroll
            for (int j2 = 0; j2 < 8; j2++) {
                int col = j2 * 8 + t * 2;
                float2 a0 = *reinterpret_cast<float2*>(&ored[(qw * 16 + g) * 64 + col]);
                float2 a1 = *reinterpret_cast<float2*>(&ored[(qw * 16 + g + 8) * 64 + col]);
                size_t r0 = (base + q0c + qw * 16 + g) * HH + col;
                *reinterpret_cast<float2*>(Outp + r0) =
                    make_float2((o[j2][0] + a0.x) * inv0, (o[j2][1] + a0.y) * inv0);
                *reinterpret_cast<float2*>(Outp + r0 + 8 * HH) =
                    make_float2((o[j2][2] + a1.x) * inv1, (o[j2][3] + a1.y) * inv1);
            }
        }
    }
}

// ---------------------------------------------------------------------------
extern "C" void kernel_launch(void* const* d_in, const int* in_sizes, int n_in,
                              void* d_out, int out_size)
{
    const float* X  = (const float*)d_in[0];
    const float* Wk = (const float*)d_in[1];
    const float* Wq = (const float*)d_in[2];
    const float* Wv = (const float*)d_in[3];
    float* Out = (float*)d_out;
    (void)in_sizes; (void)n_in; (void)out_size;

    cudaFuncSetAttribute(fused_head, cudaFuncAttributeMaxDynamicSharedMemorySize, TOT);
    fused_head<<<GRID, 256, TOT>>>(X, Wq, Wk, Wv, Out);
}

// round 17
// speedup vs baseline: 1.3052x; 1.0005x over previous
#include <cuda_runtime.h>
#include <cuda_fp16.h>
#include <cstdint>

#define BB 8
#define SS 2048
#define DD 1024
#define HH 64
#define MM (BB*SS)
#define GRID 256

// Scratch (fp16): Q pre-scaled by log2e/32; K,V hi-only
__device__ __align__(16) __half g_Qh[MM*HH];
__device__ __align__(16) __half g_Kh[MM*HH];
__device__ __align__(16) __half g_Vh[MM*HH];
// W hi (fp16 rn): [3][64][1024], mat order {Q,K,V}
__device__ __align__(16) __half g_Wh[3*HH*DD];
// grid barrier ticket counter (monotonic; stays GRID-aligned across replays)
__device__ unsigned g_bar;

// ---------------------------------------------------------------------------
// helpers
// ---------------------------------------------------------------------------
__device__ __forceinline__ uint32_t pack2h(float lo, float hi) {
    uint32_t r;
    asm("cvt.rn.f16x2.f32 %0, %1, %2;" : "=r"(r) : "f"(hi), "f"(lo));
    return r;
}

__device__ __forceinline__ void ldm_x4(uint32_t* r, uint32_t addr) {
    asm volatile("ldmatrix.sync.aligned.m8n8.x4.shared.b16 {%0,%1,%2,%3}, [%4];"
                 : "=r"(r[0]), "=r"(r[1]), "=r"(r[2]), "=r"(r[3]) : "r"(addr));
}
__device__ __forceinline__ void ldm_x4_t(uint32_t* r, uint32_t addr) {
    asm volatile("ldmatrix.sync.aligned.m8n8.x4.trans.shared.b16 {%0,%1,%2,%3}, [%4];"
                 : "=r"(r[0]), "=r"(r[1]), "=r"(r[2]), "=r"(r[3]) : "r"(addr));
}

__device__ __forceinline__ void cp16(uint32_t dst, const void* src) {
    asm volatile("cp.async.cg.shared.global [%0], [%1], 16;"
                 :: "r"(dst), "l"(src) : "memory");
}
#define CP_COMMIT() asm volatile("cp.async.commit_group;" ::: "memory")
#define CP_WAIT0()  asm volatile("cp.async.wait_group 0;" ::: "memory")

// named barrier for a 128-thread half-CTA (ids 1 and 2)
#define NBAR(idb) asm volatile("bar.sync %0, 128;" :: "r"(idb) : "memory")

// smem fp16 tiles: row stride 144 bytes (72 halves) -> ldmatrix conflict-free
#define LDB 144

__device__ __forceinline__ uint32_t ldm_addr(uint32_t base, int row0, int col0) {
    int l = threadIdx.x & 31;
    int r = row0 + (l & 7) + ((l >> 3) & 1) * 8;
    int c = col0 + (l >> 4) * 8;
    return base + r * LDB + c * 2;
}
__device__ __forceinline__ uint32_t ldm_addr_b(uint32_t base, int row0, int col0) {
    int l = threadIdx.x & 31;
    int r = row0 + (l & 7) + (l >> 4) * 8;
    int c = col0 + ((l >> 3) & 1) * 8;
    return base + r * LDB + c * 2;
}

__device__ __forceinline__ void mma_f16(float* d, const uint32_t* a, const uint32_t* b) {
    asm volatile(
        "mma.sync.aligned.m16n8k16.row.col.f32.f16.f16.f32 "
        "{%0,%1,%2,%3}, {%4,%5,%6,%7}, {%8,%9}, {%0,%1,%2,%3};"
        : "+f"(d[0]), "+f"(d[1]), "+f"(d[2]), "+f"(d[3])
        : "r"(a[0]), "r"(a[1]), "r"(a[2]), "r"(a[3]), "r"(b[0]), "r"(b[1]));
}

// 2^x via MUFU.EX2 (SFU pipe; frees ~130 issue slots/thread/kt vs FFMA poly)
__device__ __forceinline__ float fast_exp2(float x) {
    float y;
    asm("ex2.approx.f32 %0, %1;" : "=f"(y) : "f"(x));
    return y;
}

// Grid-wide barrier (GRID CTAs, single wave -> spin-safe).
__device__ __forceinline__ void grid_barrier() {
    __syncthreads();
    __threadfence();
    if (threadIdx.x == 0) {
        unsigned tck = atomicAdd(&g_bar, 1u);
        unsigned rel = (tck / GRID + 1u) * GRID;
        unsigned v;
        do {
            asm volatile("ld.volatile.global.u32 %0, [%1];"
                         : "=r"(v) : "l"(&g_bar) : "memory");
        } while (v < rel);
        __threadfence();
    }
    __syncthreads();
}

// ---------------------------------------------------------------------------
// smem layout
// ---------------------------------------------------------------------------
#define PXH   0
#define PWH   9216
#define AQ    0
#define ABUF  4608
#define PLANE 9216
#define STG   (2 * PLANE)
#define ALR   (ABUF + 2 * STG)   // 41472 (within half slice)
#define HSZ   41728              // half slice size
#define TOT   (2 * HSZ)          // 83456

__global__ __launch_bounds__(256, 2) void fused_head(
    const float* __restrict__ X,
    const float* __restrict__ Wq,
    const float* __restrict__ Wk,
    const float* __restrict__ Wv,
    float* __restrict__ Outp)
{
    extern __shared__ char sm[];
    const int tid = threadIdx.x;
    const int bid = blockIdx.x;

    // ======================= Phase A: W f32 -> f16 =========================
    {
        int gid = bid * 256 + tid;
        if (gid < 3 * 16384) {
            int mat = gid >> 14;
            int idx4 = gid & 16383;
            const float* W = (mat == 0) ? Wq : ((mat == 1) ? Wk : Wv);
            float4 v = reinterpret_cast<const float4*>(W)[idx4];
            uint32_t* ph = reinterpret_cast<uint32_t*>(g_Wh);
            ph[mat * 32768 + idx4 * 2]     = pack2h(v.x, v.y);
            ph[mat * 32768 + idx4 * 2 + 1] = pack2h(v.z, v.w);
        }
    }
    grid_barrier();

    // ======================= Phase B: projection (R13 body) ================
    {
        const uint32_t sb = (uint32_t)__cvta_generic_to_shared(sm);
        const int wid = tid >> 5, lane = tid & 31;
        const int g = lane >> 2, t = lane & 3;
        const int wm = wid >> 2, wn = wid & 3;
        const int m0 = bid * 64;

        float acc[3][2][2][4];
        #pragma unroll
        for (int a = 0; a < 3; a++)
            #pragma unroll
            for (int b = 0; b < 2; b++)
                #pragma unroll
                for (int c = 0; c < 2; c++)
                    #pragma unroll
                    for (int d = 0; d < 4; d++) acc[a][b][c][d] = 0.f;

        for (int kc = 0; kc < 16; kc++) {
            const int kbase = kc * 64;
            #pragma unroll
            for (int i = 0; i < 4; i++) {
                int id = tid + i * 256;
                int row = id >> 4, c4 = id & 15;
                float4 v = *reinterpret_cast<const float4*>(
                    X + (size_t)(m0 + row) * DD + kbase + c4 * 4);
                uint32_t off = row * LDB + c4 * 8;
                *reinterpret_cast<uint32_t*>(sm + PXH + off)     = pack2h(v.x, v.y);
                *reinterpret_cast<uint32_t*>(sm + PXH + off + 4) = pack2h(v.z, v.w);
            }
            #pragma unroll
            for (int i = 0; i < 6; i++) {
                int id = tid + i * 256;
                int row = id >> 3, c = id & 7;
                uint4 v = *reinterpret_cast<const uint4*>(
                    g_Wh + (size_t)row * DD + kbase + c * 8);
                *reinterpret_cast<uint4*>(sm + PWH + row * LDB + c * 16) = v;
            }
            __syncthreads();

            #pragma unroll
            for (int ks = 0; ks < 4; ks++) {
                uint32_t ah[2][4];
                #pragma unroll
                for (int fm = 0; fm < 2; fm++)
                    ldm_x4(ah[fm], ldm_addr(sb + PXH, wm * 32 + fm * 16, ks * 16));
                #pragma unroll
                for (int mat = 0; mat < 3; mat++) {
                    uint32_t bh[4];
                    ldm_x4(bh, ldm_addr_b(sb + PWH, mat * 64 + wn * 16, ks * 16));
                    #pragma unroll
                    for (int fm = 0; fm < 2; fm++)
                        #pragma unroll
                        for (int fn = 0; fn < 2; fn++)
                            mma_f16(acc[mat][fm][fn], ah[fm], &bh[fn * 2]);
                }
            }
            __syncthreads();
        }

        #pragma unroll
        for (int mat = 0; mat < 3; mat++) {
            __half* gh = (mat == 0) ? g_Qh : ((mat == 1) ? g_Kh : g_Vh);
            const float scl = (mat == 0) ? (1.44269504f / 32.0f) : 1.0f;
            #pragma unroll
            for (int fm = 0; fm < 2; fm++)
                #pragma unroll
                for (int fn = 0; fn < 2; fn++) {
                    const float* c = acc[mat][fm][fn];
                    int r0 = m0 + wm * 32 + fm * 16 + g;
                    int col = wn * 16 + fn * 8 + t * 2;
                    reinterpret_cast<uint32_t*>(gh)[((size_t)r0 * HH + col) >> 1] =
                        pack2h(c[0] * scl, c[1] * scl);
                    reinterpret_cast<uint32_t*>(gh)[((size_t)(r0 + 8) * HH + col) >> 1] =
                        pack2h(c[2] * scl, c[3] * scl);
                }
        }
    }
    grid_barrier();

    // ======================= Phase C: attention ============================
    {
        const int h = tid >> 7;
        const int t128 = tid & 127;
        char* smh = sm + h * HSZ;
        const uint32_t sbh = (uint32_t)__cvta_generic_to_shared(smh);
        const int wid = t128 >> 5, lane = t128 & 31;
        const int g = lane >> 2, t = lane & 3;
        const int qw = wid >> 1, kw = wid & 1;
        const int nbid = 1 + h;

        int jb;
        if (bid >= 108 && bid < 148) {
            int c = bid - 108;
            jb = h ? (335 - c) : (32 + c);
        } else {
            int s2 = (bid < 108) ? bid : (bid - 148);
            int pos = (bid < 108) ? (h ? (215 - s2) : s2)
                                  : (h ? (431 - s2) : (216 + s2));
            jb = (pos < 32) ? pos : ((pos < 256) ? pos + 40 : pos + 80);
        }
        const int qt = 31 - (jb >> 4);
        const int sub = jb & 15;
        const int b = sub >> 1, half = sub & 1;

        const int q0c = qt * 64 + half * 32;
        const size_t base = (size_t)b * SS;

        #pragma unroll
        for (int i2 = 0; i2 < 8; i2++) {
            int id = t128 + i2 * 128;
            int plane = id >> 9, rem = id & 511;
            int row = rem >> 3, c = rem & 7;
            const __half* src = (plane == 0) ? g_Kh : g_Vh;
            cp16(sbh + ABUF + plane * PLANE + row * LDB + c * 16,
                 src + (base + row) * HH + c * 8);
        }
        CP_COMMIT();

        #pragma unroll
        for (int i2 = 0; i2 < 2; i2++) {
            int id = t128 + i2 * 128;
            int row = id >> 3, c = id & 7;
            *reinterpret_cast<uint4*>(smh + AQ + row * LDB + c * 16) =
                *reinterpret_cast<const uint4*>(g_Qh + (base + q0c + row) * HH + c * 8);
        }
        NBAR(nbid);
        uint32_t qa[4][4];
        #pragma unroll
        for (int hs = 0; hs < 4; hs++)
            ldm_x4(qa[hs], ldm_addr(sbh + AQ, qw * 16, hs * 16));

        float o[8][4];
        #pragma unroll
        for (int i2 = 0; i2 < 8; i2++)
            #pragma unroll
            for (int j2 = 0; j2 < 4; j2++) o[i2][j2] = 0.f;
        float ls[4] = {0.f, 0.f, 0.f, 0.f};  // rowsum acc via P*ones mma
        const uint32_t ones2[2] = {0x3C003C00u, 0x3C003C00u};

        for (int kt = 0; kt <= qt; kt++) {
            const int k0 = kt * 64;
            CP_WAIT0();
            NBAR(nbid);

            if (kt < qt) {
                const int kn = k0 + 64;
                const uint32_t dstg = sbh + ABUF + ((kt + 1) & 1) * STG;
                #pragma unroll
                for (int i2 = 0; i2 < 8; i2++) {
                    int id = t128 + i2 * 128;
                    int plane = id >> 9, rem = id & 511;
                    int row = rem >> 3, c = rem & 7;
                    const __half* src = (plane == 0) ? g_Kh : g_Vh;
                    cp16(dstg + plane * PLANE + row * LDB + c * 16,
                         src + (base + kn + row) * HH + c * 8);
                }
            }
            CP_COMMIT();

            if (kt == qt && half == 0 && kw == 1) continue;

            const uint32_t stg = sbh + ABUF + (kt & 1) * STG;
            const uint32_t sKH = stg, sVH = stg + PLANE;

            float s[4][4];
            #pragma unroll
            for (int i2 = 0; i2 < 4; i2++)
                #pragma unroll
                for (int j2 = 0; j2 < 4; j2++) s[i2][j2] = 0.f;

            #pragma unroll
            for (int hs = 0; hs < 4; hs++) {
                uint32_t bh[4], bh2[4];
                ldm_x4(bh,  ldm_addr_b(sKH, kw * 32,      hs * 16));
                ldm_x4(bh2, ldm_addr_b(sKH, kw * 32 + 16, hs * 16));
                #pragma unroll
                for (int fn = 0; fn < 2; fn++) {
                    mma_f16(s[fn],     qa[hs], &bh[fn * 2]);
                    mma_f16(s[2 + fn], qa[hs], &bh2[fn * 2]);
                }
            }

            if (kt == qt) {
                #pragma unroll
                for (int f = 0; f < 4; f++) {
                    int kg = k0 + kw * 32 + f * 8 + t * 2;
                    int qg0 = q0c + qw * 16 + g, qg1 = qg0 + 8;
                    if (kg     > qg0) s[f][0] = -126.f;
                    if (kg + 1 > qg0) s[f][1] = -126.f;
                    if (kg     > qg1) s[f][2] = -126.f;
                    if (kg + 1 > qg1) s[f][3] = -126.f;
                }
            }

            // P = 2^{S'} (MUFU); pack to fp16 A-frags; rowsums via P*ones mma
            uint32_t pah[2][4];
            #pragma unroll
            for (int ks2 = 0; ks2 < 2; ks2++) {
                #pragma unroll
                for (int ff = 0; ff < 2; ff++) {
                    const int f = ks2 * 2 + ff;
                    float p0 = fast_exp2(s[f][0]);
                    float p1 = fast_exp2(s[f][1]);
                    float p2 = fast_exp2(s[f][2]);
                    float p3 = fast_exp2(s[f][3]);
                    pah[ks2][ff * 2]     = pack2h(p0, p1);
                    pah[ks2][ff * 2 + 1] = pack2h(p2, p3);
                }
                mma_f16(ls, pah[ks2], ones2);
            }

            #pragma unroll
            for (int ks2 = 0; ks2 < 2; ks2++) {
                uint32_t vh[4][4];
                #pragma unroll
                for (int c = 0; c < 4; c++)
                    ldm_x4_t(vh[c], ldm_addr(sVH, kw * 32 + ks2 * 16, c * 16));
                #pragma unroll
                for (int j2 = 0; j2 < 8; j2++)
                    mma_f16(o[j2], pah[ks2], &vh[j2 >> 1][(j2 & 1) * 2]);
            }
        }
        NBAR(nbid);

        // ls[0] = rowsum(row g), ls[2] = rowsum(row g+8), identical across quad
        float* lred = reinterpret_cast<float*>(smh + ALR);
        if (t == 0) {
            lred[(qw * 2 + kw) * 16 + g]     = ls[0];
            lred[(qw * 2 + kw) * 16 + 8 + g] = ls[2];
        }
        float* ored = reinterpret_cast<float*>(smh);
        if (kw == 1) {
            #pragma unroll
            for (int j2 = 0; j2 < 8; j2++) {
                int col = j2 * 8 + t * 2;
                *reinterpret_cast<float2*>(&ored[(qw * 16 + g) * 64 + col]) =
                    make_float2(o[j2][0], o[j2][1]);
                *reinterpret_cast<float2*>(&ored[(qw * 16 + g + 8) * 64 + col]) =
                    make_float2(o[j2][2], o[j2][3]);
            }
        }
        NBAR(nbid);

        if (kw == 0) {
            float inv0 = 1.f / (lred[(qw * 2) * 16 + g]     + lred[(qw * 2 + 1) * 16 + g]);
            float inv1 = 1.f / (lred[(qw * 2) * 16 + 8 + g] + lred[(qw * 2 + 1) * 16 + 8 + g]);
            #pragma unroll
            for (int j2 = 0; j2 < 8; j2++) {
                int col = j2 * 8 + t * 2;
                float2 a0 = *reinterpret_cast<float2*>(&ored[(qw * 16 + g) * 64 + col]);
                float2 a1 = *reinterpret_cast<float2*>(&ored[(qw * 16 + g + 8) * 64 + col]);
                size_t r0 = (base + q0c + qw * 16 + g) * HH + col;
                *reinterpret_cast<float2*>(Outp + r0) =
                    make_float2((o[j2][0] + a0.x) * inv0, (o[j2][1] + a0.y) * inv0);
                *reinterpret_cast<float2*>(Outp + r0 + 8 * HH) =
                    make_float2((o[j2][2] + a1.x) * inv1, (o[j2][3] + a1.y) * inv1);
            }
        }
    }
}

// ---------------------------------------------------------------------------
extern "C" void kernel_launch(void* const* d_in, const int* in_sizes, int n_in,
                              void* d_out, int out_size)
{
    const float* X  = (const float*)d_in[0];
    const float* Wk = (const float*)d_in[1];
    const float* Wq = (const float*)d_in[2];
    const float* Wv = (const float*)d_in[3];
    float* Out = (float*)d_out;
    (void)in_sizes; (void)n_in; (void)out_size;

    cudaFuncSetAttribute(fused_head, cudaFuncAttributeMaxDynamicSharedMemorySize, TOT);
    fused_head<<<GRID, 256, TOT>>>(X, Wq, Wk, Wv, Out);
}